// round 1
// baseline (speedup 1.0000x reference)
#include <cuda_runtime.h>
#include <cuda_bf16.h>

// Problem constants (fixed shapes for this problem)
#define Dd 64
#define TE 64          // rows (edges/nodes) per block tile
#define NMAX 50000
#define EMAX 500000
#define EPS 1e-5f

// ---------------- device scratch (static, no allocation) ----------------
__device__ float g_h[NMAX * Dd];
__device__ float g_aggr[NMAX * Dd];
__device__ float g_u[NMAX * Dd];
__device__ float g_m[(size_t)EMAX * Dd];   // 128 MB edge intermediate (in-place reuse)
__device__ double g_sum[Dd];
__device__ double g_sumsq[Dd];
__device__ float g_scale[Dd];
__device__ float g_shift[Dd];

// ---------------- init: h = relu(x@Win + bin + prev@Whist + bhist) ----------------
__global__ void init_h_kernel(const float* __restrict__ x, const float* __restrict__ prev,
                              const float* __restrict__ wi, const float* __restrict__ bi,
                              const float* __restrict__ wh, const float* __restrict__ bh,
                              int N) {
    int i = blockIdx.x * blockDim.x + threadIdx.x;
    if (i >= N * Dd) return;
    int n = i >> 6, c = i & 63;
    float acc = bi[c] + bh[c];
    const float* xr = x + n * 11;
#pragma unroll
    for (int k = 0; k < 11; k++) acc = fmaf(xr[k], wi[k * Dd + c], acc);
    const float* pr = prev + n * Dd;
#pragma unroll 8
    for (int k = 0; k < Dd; k++) acc = fmaf(pr[k], wh[k * Dd + c], acc);
    g_h[i] = fmaxf(acc, 0.f);
}

// ---------------- generic fused GEMM + BN-stats kernel ----------------
// MODE 0: edge stage1: in = cat(h[dst], h[src], edge_attr), K=132
// MODE 1: affine+relu of inA rows (K=64), in-place capable
// MODE 2: node stage1: in = cat(h, aggr), K=128
template <int K, int MODE>
__global__ __launch_bounds__(256)
void gemm_bn_kernel(const float* __restrict__ W, const float* __restrict__ bias,
                    const float* __restrict__ inA, const float* __restrict__ inB,
                    const int* __restrict__ dstIdx, const int* __restrict__ srcIdx,
                    const float* __restrict__ scale, const float* __restrict__ shift,
                    float* __restrict__ out, int M) {
    extern __shared__ float smem[];
    float* sW = smem;                 // K*64
    float* sIn = smem + K * 64;       // K*TE (transposed: [k][e])
    float* sScale = sIn + K * TE;     // K
    float* sShift = sScale + K;       // K
    double* sSum = (double*)(sShift + K);  // 64
    double* sSq = sSum + 64;               // 64

    int tid = threadIdx.x;
    for (int idx = tid; idx < K * 64; idx += 256) sW[idx] = W[idx];
    if (MODE == 1) {
        for (int idx = tid; idx < K; idx += 256) { sScale[idx] = scale[idx]; sShift[idx] = shift[idx]; }
    }
    if (tid < 64) { sSum[tid] = 0.0; sSq[tid] = 0.0; }
    __syncthreads();

    const int cBase = (tid & 15) * 4;   // 4 output cols per thread
    const int eBase = (tid >> 4) * 4;   // 4 rows per thread

    float ls0 = 0, ls1 = 0, ls2 = 0, ls3 = 0;
    float lq0 = 0, lq1 = 0, lq2 = 0, lq3 = 0;
    const float b0 = bias[cBase + 0], b1 = bias[cBase + 1],
                b2 = bias[cBase + 2], b3 = bias[cBase + 3];

    const int nTiles = (M + TE - 1) / TE;
    for (int tile = blockIdx.x; tile < nTiles; tile += gridDim.x) {
        const int base = tile * TE;
        __syncthreads();  // previous tile's compute done before restaging
        for (int idx = tid; idx < K * TE; idx += 256) {
            int e = idx / K;
            int k = idx - e * K;
            int ge = base + e;
            float v = 0.f;
            if (ge < M) {
                if (MODE == 0) {
                    if (k < 64)       v = inA[dstIdx[ge] * Dd + k];
                    else if (k < 128) v = inA[srcIdx[ge] * Dd + (k - 64)];
                    else              v = inB[ge * 4 + (k - 128)];
                } else if (MODE == 1) {
                    v = fmaxf(fmaf(inA[ge * K + k], sScale[k], sShift[k]), 0.f);
                } else {  // MODE 2
                    if (k < 64) v = inA[ge * Dd + k];
                    else        v = inB[ge * Dd + (k - 64)];
                }
            }
            sIn[k * TE + e] = v;
        }
        __syncthreads();

        float4 a0c = {0, 0, 0, 0}, a1c = {0, 0, 0, 0}, a2c = {0, 0, 0, 0}, a3c = {0, 0, 0, 0};
#pragma unroll 4
        for (int k = 0; k < K; k++) {
            const float4 a = *(const float4*)(sIn + k * TE + eBase);
            const float4 w = *(const float4*)(sW + k * 64 + cBase);
            a0c.x = fmaf(a.x, w.x, a0c.x); a0c.y = fmaf(a.x, w.y, a0c.y);
            a0c.z = fmaf(a.x, w.z, a0c.z); a0c.w = fmaf(a.x, w.w, a0c.w);
            a1c.x = fmaf(a.y, w.x, a1c.x); a1c.y = fmaf(a.y, w.y, a1c.y);
            a1c.z = fmaf(a.y, w.z, a1c.z); a1c.w = fmaf(a.y, w.w, a1c.w);
            a2c.x = fmaf(a.z, w.x, a2c.x); a2c.y = fmaf(a.z, w.y, a2c.y);
            a2c.z = fmaf(a.z, w.z, a2c.z); a2c.w = fmaf(a.z, w.w, a2c.w);
            a3c.x = fmaf(a.w, w.x, a3c.x); a3c.y = fmaf(a.w, w.y, a3c.y);
            a3c.z = fmaf(a.w, w.z, a3c.z); a3c.w = fmaf(a.w, w.w, a3c.w);
        }

#pragma unroll
        for (int e = 0; e < 4; e++) {
            int ge = base + eBase + e;
            if (ge >= M) break;
            float4 o = (e == 0) ? a0c : (e == 1) ? a1c : (e == 2) ? a2c : a3c;
            o.x += b0; o.y += b1; o.z += b2; o.w += b3;
            *(float4*)(out + (size_t)ge * Dd + cBase) = o;
            ls0 += o.x; ls1 += o.y; ls2 += o.z; ls3 += o.w;
            lq0 += o.x * o.x; lq1 += o.y * o.y; lq2 += o.z * o.z; lq3 += o.w * o.w;
        }
    }

    __syncthreads();
    atomicAdd(&sSum[cBase + 0], (double)ls0); atomicAdd(&sSq[cBase + 0], (double)lq0);
    atomicAdd(&sSum[cBase + 1], (double)ls1); atomicAdd(&sSq[cBase + 1], (double)lq1);
    atomicAdd(&sSum[cBase + 2], (double)ls2); atomicAdd(&sSq[cBase + 2], (double)lq2);
    atomicAdd(&sSum[cBase + 3], (double)ls3); atomicAdd(&sSq[cBase + 3], (double)lq3);
    __syncthreads();
    if (tid < 64) {
        atomicAdd(&g_sum[tid], sSum[tid]);
        atomicAdd(&g_sumsq[tid], sSq[tid]);
    }
}

// ---------------- BN finalize: stats -> (scale, shift); zero accumulators ----------------
__global__ void finalize_bn_kernel(const float* __restrict__ g, const float* __restrict__ be,
                                   double invCount) {
    int c = threadIdx.x;
    if (c >= Dd) return;
    double s = g_sum[c], q = g_sumsq[c];
    double m = s * invCount;
    double var = q * invCount - m * m;
    if (var < 0.0) var = 0.0;
    float rstd = rsqrtf((float)var + EPS);
    float sc = g[c] * rstd;
    g_scale[c] = sc;
    g_shift[c] = be[c] - (float)m * sc;
    g_sum[c] = 0.0;
    g_sumsq[c] = 0.0;
}

// ---------------- zero aggr ----------------
__global__ void zero_aggr_kernel(int total) {
    int i = blockIdx.x * blockDim.x + threadIdx.x;
    if (i < total) g_aggr[i] = 0.f;
}

// ---------------- scatter: aggr[dst] += relu(affine(m2)) ----------------
__global__ void scatter_kernel(const float* __restrict__ m, const int* __restrict__ dst,
                               const float* __restrict__ scale, const float* __restrict__ shift,
                               int E) {
    int idx = blockIdx.x * blockDim.x + threadIdx.x;
    int total = E * 16;
    if (idx >= total) return;
    int e = idx >> 4, q = idx & 15;
    float4 v = ((const float4*)m)[(size_t)e * 16 + q];
    float4 sc = ((const float4*)scale)[q];
    float4 sh = ((const float4*)shift)[q];
    float* a = g_aggr + (size_t)dst[e] * Dd + q * 4;
    atomicAdd(a + 0, fmaxf(fmaf(v.x, sc.x, sh.x), 0.f));
    atomicAdd(a + 1, fmaxf(fmaf(v.y, sc.y, sh.y), 0.f));
    atomicAdd(a + 2, fmaxf(fmaf(v.z, sc.z, sh.z), 0.f));
    atomicAdd(a + 3, fmaxf(fmaf(v.w, sc.w, sh.w), 0.f));
}

// ---------------- h += relu(affine(u2)) ----------------
__global__ void h_update_kernel(const float* __restrict__ u, const float* __restrict__ scale,
                                const float* __restrict__ shift, int total) {
    int i = blockIdx.x * blockDim.x + threadIdx.x;
    if (i >= total) return;
    int c = i & 63;
    g_h[i] += fmaxf(fmaf(u[i], scale[c], shift[c]), 0.f);
}

// ---------------- column sums of h (for graph mean) ----------------
__global__ void colsum_kernel(int N) {
    __shared__ double s[Dd];
    int tid = threadIdx.x;
    if (tid < Dd) s[tid] = 0.0;
    __syncthreads();
    int c = tid & 63;
    int rowsPerBlk = blockDim.x >> 6;
    float part = 0.f;
    for (int n = blockIdx.x * rowsPerBlk + (tid >> 6); n < N; n += gridDim.x * rowsPerBlk)
        part += g_h[(size_t)n * Dd + c];
    atomicAdd(&s[c], (double)part);
    __syncthreads();
    if (tid < Dd) atomicAdd(&g_sum[tid], s[tid]);
}

__global__ void graph_out_kernel(const float* __restrict__ gw, const float* __restrict__ gb,
                                 float* __restrict__ out, double invN) {
    __shared__ float partial[Dd];
    int c = threadIdx.x;
    if (c < Dd) {
        partial[c] = (float)(g_sum[c] * invN) * gw[c];
        g_sum[c] = 0.0;
    }
    __syncthreads();
    if (c == 0) {
        float s = 0.f;
        for (int i = 0; i < Dd; i++) s += partial[i];
        out[0] = s + gb[0];
    }
}

__global__ void node_out_kernel(const float* __restrict__ nw, const float* __restrict__ nb,
                                float* __restrict__ out, int N) {
    int idx = blockIdx.x * blockDim.x + threadIdx.x;
    if (idx >= N * 5) return;
    int n = idx / 5, o = idx - n * 5;
    float acc = nb[o];
    const float* hr = g_h + (size_t)n * Dd;
#pragma unroll 8
    for (int k = 0; k < Dd; k++) acc = fmaf(hr[k], nw[k * 5 + o], acc);
    out[idx] = acc;
}

__global__ void copy_h_kernel(float* __restrict__ out, int total) {
    int i = blockIdx.x * blockDim.x + threadIdx.x;
    if (i < total) out[i] = g_h[i];
}

// ---------------- host launcher ----------------
extern "C" void kernel_launch(void* const* d_in, const int* in_sizes, int n_in,
                              void* d_out, int out_size) {
    const float* x       = (const float*)d_in[0];
    const int*   ei      = (const int*)d_in[1];
    const float* eattr   = (const float*)d_in[2];
    const float* prev_h  = (const float*)d_in[3];
    const float* lin_in_w = (const float*)d_in[4];
    const float* lin_in_b = (const float*)d_in[5];
    const float* hist_w   = (const float*)d_in[6];
    const float* hist_b   = (const float*)d_in[7];
    const float* msg_w1 = (const float*)d_in[8];
    const float* msg_b1 = (const float*)d_in[9];
    const float* msg_g1 = (const float*)d_in[10];
    const float* msg_be1 = (const float*)d_in[11];
    const float* msg_w2 = (const float*)d_in[12];
    const float* msg_b2 = (const float*)d_in[13];
    const float* msg_g2 = (const float*)d_in[14];
    const float* msg_be2 = (const float*)d_in[15];
    const float* upd_w1 = (const float*)d_in[16];
    const float* upd_b1 = (const float*)d_in[17];
    const float* upd_g1 = (const float*)d_in[18];
    const float* upd_be1 = (const float*)d_in[19];
    const float* upd_w2 = (const float*)d_in[20];
    const float* upd_b2 = (const float*)d_in[21];
    const float* upd_g2 = (const float*)d_in[22];
    const float* upd_be2 = (const float*)d_in[23];
    const float* graph_w = (const float*)d_in[24];
    const float* graph_b = (const float*)d_in[25];
    const float* node_w  = (const float*)d_in[26];
    const float* node_b  = (const float*)d_in[27];

    const int N = in_sizes[0] / 11;
    const int E = in_sizes[1] / 2;
    const int* src = ei;       // edge_index[0]
    const int* dst = ei + E;   // edge_index[1]

    float* out = (float*)d_out;
    float* out_graph = out;
    float* out_node = out + 1;
    float* out_h = out + 1 + (size_t)N * 5;

    // device-symbol addresses
    float *p_h, *p_aggr, *p_u, *p_m, *p_scale, *p_shift;
    cudaGetSymbolAddress((void**)&p_h, g_h);
    cudaGetSymbolAddress((void**)&p_aggr, g_aggr);
    cudaGetSymbolAddress((void**)&p_u, g_u);
    cudaGetSymbolAddress((void**)&p_m, g_m);
    cudaGetSymbolAddress((void**)&p_scale, g_scale);
    cudaGetSymbolAddress((void**)&p_shift, g_shift);

    // dynamic smem sizes: (K*128 + 2K) floats + 128 doubles
    const int smem132 = (132 * 128 + 2 * 132) * 4 + 1024;
    const int smem128 = (128 * 128 + 2 * 128) * 4 + 1024;
    const int smem64  = (64 * 128 + 2 * 64) * 4 + 1024;
    cudaFuncSetAttribute(gemm_bn_kernel<132, 0>, cudaFuncAttributeMaxDynamicSharedMemorySize, smem132);
    cudaFuncSetAttribute(gemm_bn_kernel<128, 2>, cudaFuncAttributeMaxDynamicSharedMemorySize, smem128);
    cudaFuncSetAttribute(gemm_bn_kernel<64, 1>,  cudaFuncAttributeMaxDynamicSharedMemorySize, smem64);

    const int GRID_BIG = 148 * 3;   // 3 blocks/SM at ~68KB smem
    const int GRID_MED = 148 * 6;   // 6 blocks/SM at ~34KB smem
    const double invE = 1.0 / (double)E;
    const double invN = 1.0 / (double)N;

    // h0
    init_h_kernel<<<(N * Dd + 255) / 256, 256>>>(x, prev_h, lin_in_w, lin_in_b, hist_w, hist_b, N);

    for (int l = 0; l < 4; l++) {
        // ---- message MLP stage 1: m1 = cat(h[dst],h[src],ea) @ W1 + b1 ----
        gemm_bn_kernel<132, 0><<<GRID_BIG, 256, smem132>>>(
            msg_w1 + (size_t)l * 132 * Dd, msg_b1 + l * Dd,
            p_h, eattr, dst, src, nullptr, nullptr, p_m, E);
        finalize_bn_kernel<<<1, 64>>>(msg_g1 + l * Dd, msg_be1 + l * Dd, invE);

        // ---- message MLP stage 2: m2 = bn_relu(m1) @ W2 + b2 (in-place over g_m) ----
        gemm_bn_kernel<64, 1><<<GRID_MED, 256, smem64>>>(
            msg_w2 + (size_t)l * 64 * Dd, msg_b2 + l * Dd,
            p_m, nullptr, nullptr, nullptr, p_scale, p_shift, p_m, E);
        finalize_bn_kernel<<<1, 64>>>(msg_g2 + l * Dd, msg_be2 + l * Dd, invE);

        // ---- aggr = segment_sum(bn_relu(m2), dst) ----
        zero_aggr_kernel<<<(N * Dd + 255) / 256, 256>>>(N * Dd);
        scatter_kernel<<<(E * 16 + 255) / 256, 256>>>(p_m, dst, p_scale, p_shift, E);

        // ---- update MLP stage 1: u1 = cat(h, aggr) @ Wu1 + b ----
        gemm_bn_kernel<128, 2><<<GRID_BIG, 256, smem128>>>(
            upd_w1 + (size_t)l * 128 * Dd, upd_b1 + l * Dd,
            p_h, p_aggr, nullptr, nullptr, nullptr, nullptr, p_u, N);
        finalize_bn_kernel<<<1, 64>>>(upd_g1 + l * Dd, upd_be1 + l * Dd, invN);

        // ---- update MLP stage 2: u2 = bn_relu(u1) @ Wu2 + b (in-place over g_u) ----
        gemm_bn_kernel<64, 1><<<GRID_MED, 256, smem64>>>(
            upd_w2 + (size_t)l * 64 * Dd, upd_b2 + l * Dd,
            p_u, nullptr, nullptr, nullptr, p_scale, p_shift, p_u, N);
        finalize_bn_kernel<<<1, 64>>>(upd_g2 + l * Dd, upd_be2 + l * Dd, invN);

        // ---- h += relu(affine(u2)) ----
        h_update_kernel<<<(N * Dd + 255) / 256, 256>>>(p_u, p_scale, p_shift, N * Dd);
    }

    // ---- outputs ----
    colsum_kernel<<<444, 256>>>(N);
    graph_out_kernel<<<1, 64>>>(graph_w, graph_b, out_graph, invN);
    node_out_kernel<<<(N * 5 + 255) / 256, 256>>>(node_w, node_b, out_node, N);
    copy_h_kernel<<<(N * Dd + 255) / 256, 256>>>(out_h, N * Dd);
}

// round 2
// speedup vs baseline: 1.3468x; 1.3468x over previous
#include <cuda_runtime.h>

// Problem constants (fixed shapes)
#define Dd 64
#define TE 128         // rows per block tile
#define NMAX 50000
#define EMAX 500000
#define EPS 1e-5f

typedef unsigned long long u64;

// ---------------- device scratch (static, no allocation) ----------------
__device__ __align__(16) float g_h[NMAX * Dd];
__device__ __align__(16) float g_aggr[NMAX * Dd];
__device__ __align__(16) float g_u[NMAX * Dd];
__device__ __align__(16) float g_m[(size_t)EMAX * Dd];
__device__ double g_sum[Dd];
__device__ double g_sumsq[Dd];
__device__ float g_scale[Dd];
__device__ float g_shift[Dd];

// ---------------- f32x2 helpers ----------------
__device__ __forceinline__ u64 pack2(float lo, float hi) {
    u64 r; asm("mov.b64 %0, {%1,%2};" : "=l"(r) : "f"(lo), "f"(hi)); return r;
}
__device__ __forceinline__ void unpack2(u64 v, float& lo, float& hi) {
    asm("mov.b64 {%0,%1}, %2;" : "=f"(lo), "=f"(hi) : "l"(v));
}
__device__ __forceinline__ void ffma2(u64& d, u64 a, u64 b) {
    asm("fma.rn.f32x2 %0, %1, %2, %0;" : "+l"(d) : "l"(a), "l"(b));
}
__device__ __forceinline__ void fadd2(u64& d, u64 a) {
    asm("add.rn.f32x2 %0, %0, %1;" : "+l"(d) : "l"(a));
}
__device__ __forceinline__ void fsq2(u64& d, u64 a) {
    asm("fma.rn.f32x2 %0, %1, %1, %0;" : "+l"(d) : "l"(a));
}

// ---------------- init: h = relu(x@Win + bin + prev@Whist + bhist) ----------------
__global__ void init_h_kernel(const float* __restrict__ x, const float* __restrict__ prev,
                              const float* __restrict__ wi, const float* __restrict__ bi,
                              const float* __restrict__ wh, const float* __restrict__ bh,
                              int N) {
    int i = blockIdx.x * blockDim.x + threadIdx.x;
    if (i >= N * Dd) return;
    int n = i >> 6, c = i & 63;
    float acc = bi[c] + bh[c];
    const float* xr = x + n * 11;
#pragma unroll
    for (int k = 0; k < 11; k++) acc = fmaf(xr[k], wi[k * Dd + c], acc);
    const float* pr = prev + n * Dd;
#pragma unroll 8
    for (int k = 0; k < Dd; k++) acc = fmaf(pr[k], wh[k * Dd + c], acc);
    g_h[i] = fmaxf(acc, 0.f);
}

// ---------------- fused GEMM + BN-stats kernel (f32x2) ----------------
// MODE 0: edge stage1: in = cat(h[dst], h[src], edge_attr), K=132
// MODE 1: affine+relu(inA) rows (K=64), in-place capable
// MODE 2: node stage1: in = cat(h, aggr), K=128
template <int K, int MODE>
__global__ __launch_bounds__(128)
void gemm_bn_kernel(const float* __restrict__ W, const float* __restrict__ bias,
                    const float* __restrict__ inA, const float* __restrict__ inB,
                    const int* __restrict__ dstIdx, const int* __restrict__ srcIdx,
                    const float* __restrict__ scale, const float* __restrict__ shift,
                    float* __restrict__ out, int M) {
    constexpr int Kv4 = K / 4;
    constexpr int Kv4p = Kv4 + 1;   // padded row stride (float4 units) -> bank rotation

    extern __shared__ float smem[];
    float4* sIn4 = (float4*)smem;                          // TE * Kv4p float4
    float*  sW   = smem + TE * Kv4p * 4;                   // K * 64 floats
    double* sSum = (double*)(sW + K * 64);                 // 64
    double* sSq  = sSum + 64;                              // 64
    int* sDst = (int*)(sSq + 64);                          // 128
    int* sSrc = sDst + 128;                                // 128

    const int tid = threadIdx.x;
    const int cg = tid & 7;
    const int cBase = cg * 8;            // 8 output cols per thread
    const int egrp = tid >> 3;           // 0..15
    const int band = (egrp >> 2) << 5;   // 32-row band per warp
    const int elane = egrp & 3;          // row lane within band (stride-4 interleave)

    // stage weights once (constant across tiles)
    {
        const float4* W4 = (const float4*)W;
        float4* sW4 = (float4*)sW;
        for (int i = tid; i < K * 16; i += 128) sW4[i] = W4[i];
    }
    if (tid < 64) { sSum[tid] = 0.0; sSq[tid] = 0.0; }

    // bias as f32x2 pairs
    u64 bb[4];
    {
        const ulonglong2* bp = (const ulonglong2*)(bias + cBase);
        ulonglong2 t0 = bp[0], t1 = bp[1];
        bb[0] = t0.x; bb[1] = t0.y; bb[2] = t1.x; bb[3] = t1.y;
    }

    u64 ls[4] = {0, 0, 0, 0}, lq[4] = {0, 0, 0, 0};

    const float4* inA4 = (const float4*)inA;
    const float4* inB4 = (const float4*)inB;

    const int nTiles = (M + TE - 1) / TE;
    for (int tile = blockIdx.x; tile < nTiles; tile += gridDim.x) {
        const int base = tile * TE;

        if (MODE == 0) {
            int ge = base + tid;
            bool ok = ge < M;
            sDst[tid] = ok ? dstIdx[ge] : 0;
            sSrc[tid] = ok ? srcIdx[ge] : 0;
        }
        __syncthreads();

        // ---- stage input tile (row-major float4, padded rows) ----
        for (int idx = tid; idx < TE * Kv4; idx += 128) {
            int e = idx / Kv4;
            int kq = idx - e * Kv4;
            int ge = base + e;
            float4 v = make_float4(0.f, 0.f, 0.f, 0.f);
            if (ge < M) {
                if (MODE == 0) {
                    if (kq < 16)      v = inA4[sDst[e] * 16 + kq];
                    else if (kq < 32) v = inA4[sSrc[e] * 16 + (kq - 16)];
                    else              v = inB4[ge];
                } else if (MODE == 1) {
                    v = inA4[ge * 16 + kq];
                    float4 sc = ((const float4*)scale)[kq];
                    float4 sh = ((const float4*)shift)[kq];
                    v.x = fmaxf(fmaf(v.x, sc.x, sh.x), 0.f);
                    v.y = fmaxf(fmaf(v.y, sc.y, sh.y), 0.f);
                    v.z = fmaxf(fmaf(v.z, sc.z, sh.z), 0.f);
                    v.w = fmaxf(fmaf(v.w, sc.w, sh.w), 0.f);
                } else {
                    if (kq < 16) v = inA4[ge * 16 + kq];
                    else         v = inB4[ge * 16 + (kq - 16)];
                }
            }
            sIn4[e * Kv4p + kq] = v;
        }
        __syncthreads();

        // ---- compute: 8 rows x 8 cols per thread, f32x2 over col pairs ----
        u64 acc[8][4];
#pragma unroll
        for (int i = 0; i < 8; i++) {
            acc[i][0] = bb[0]; acc[i][1] = bb[1]; acc[i][2] = bb[2]; acc[i][3] = bb[3];
        }

#pragma unroll 1
        for (int kq = 0; kq < Kv4; kq++) {
            float4 a4[8];
#pragma unroll
            for (int i = 0; i < 8; i++)
                a4[i] = sIn4[(band + elane + (i << 2)) * Kv4p + kq];
#pragma unroll
            for (int kr = 0; kr < 4; kr++) {
                const int k = kq * 4 + kr;
                const ulonglong2* wp = (const ulonglong2*)(sW + k * 64 + cBase);
                ulonglong2 w01 = wp[0];
                ulonglong2 w23 = wp[1];
#pragma unroll
                for (int i = 0; i < 8; i++) {
                    float av = (kr == 0) ? a4[i].x : (kr == 1) ? a4[i].y
                             : (kr == 2) ? a4[i].z : a4[i].w;
                    u64 ap = pack2(av, av);
                    ffma2(acc[i][0], ap, w01.x);
                    ffma2(acc[i][1], ap, w01.y);
                    ffma2(acc[i][2], ap, w23.x);
                    ffma2(acc[i][3], ap, w23.y);
                }
            }
        }

        // ---- epilogue: store + BN stats ----
#pragma unroll
        for (int i = 0; i < 8; i++) {
            int e = band + elane + (i << 2);
            int ge = base + e;
            if (ge < M) {
                ulonglong2* o = (ulonglong2*)(out + (size_t)ge * Dd + cBase);
                ulonglong2 s0; s0.x = acc[i][0]; s0.y = acc[i][1];
                ulonglong2 s1; s1.x = acc[i][2]; s1.y = acc[i][3];
                o[0] = s0; o[1] = s1;
#pragma unroll
                for (int p = 0; p < 4; p++) { fadd2(ls[p], acc[i][p]); fsq2(lq[p], acc[i][p]); }
            }
        }
        __syncthreads();
    }

    // ---- reduce stats: regs -> smem doubles -> global doubles ----
#pragma unroll
    for (int p = 0; p < 4; p++) {
        float lo, hi;
        unpack2(ls[p], lo, hi);
        atomicAdd(&sSum[cBase + 2 * p], (double)lo);
        atomicAdd(&sSum[cBase + 2 * p + 1], (double)hi);
        unpack2(lq[p], lo, hi);
        atomicAdd(&sSq[cBase + 2 * p], (double)lo);
        atomicAdd(&sSq[cBase + 2 * p + 1], (double)hi);
    }
    __syncthreads();
    if (tid < 64) {
        atomicAdd(&g_sum[tid], sSum[tid]);
        atomicAdd(&g_sumsq[tid], sSq[tid]);
    }
}

// ---------------- BN finalize: stats -> (scale, shift); zero accumulators ----------------
__global__ void finalize_bn_kernel(const float* __restrict__ g, const float* __restrict__ be,
                                   double invCount) {
    int c = threadIdx.x;
    if (c >= Dd) return;
    double s = g_sum[c], q = g_sumsq[c];
    double m = s * invCount;
    double var = q * invCount - m * m;
    if (var < 0.0) var = 0.0;
    float rstd = rsqrtf((float)var + EPS);
    float sc = g[c] * rstd;
    g_scale[c] = sc;
    g_shift[c] = be[c] - (float)m * sc;
    g_sum[c] = 0.0;
    g_sumsq[c] = 0.0;
}

// ---------------- zero aggr ----------------
__global__ void zero_aggr_kernel(int total) {
    int i = blockIdx.x * blockDim.x + threadIdx.x;
    if (i < total) g_aggr[i] = 0.f;
}

// ---------------- scatter: aggr[dst] += relu(affine(m2)) ----------------
__global__ void scatter_kernel(const float* __restrict__ m, const int* __restrict__ dst,
                               const float* __restrict__ scale, const float* __restrict__ shift,
                               int E) {
    int idx = blockIdx.x * blockDim.x + threadIdx.x;
    int total = E * 16;
    if (idx >= total) return;
    int e = idx >> 4, q = idx & 15;
    float4 v = ((const float4*)m)[(size_t)e * 16 + q];
    float4 sc = ((const float4*)scale)[q];
    float4 sh = ((const float4*)shift)[q];
    float* a = g_aggr + (size_t)dst[e] * Dd + q * 4;
    atomicAdd(a + 0, fmaxf(fmaf(v.x, sc.x, sh.x), 0.f));
    atomicAdd(a + 1, fmaxf(fmaf(v.y, sc.y, sh.y), 0.f));
    atomicAdd(a + 2, fmaxf(fmaf(v.z, sc.z, sh.z), 0.f));
    atomicAdd(a + 3, fmaxf(fmaf(v.w, sc.w, sh.w), 0.f));
}

// ---------------- h += relu(affine(u2)) ----------------
__global__ void h_update_kernel(const float* __restrict__ u, const float* __restrict__ scale,
                                const float* __restrict__ shift, int total) {
    int i = blockIdx.x * blockDim.x + threadIdx.x;
    if (i >= total) return;
    int c = i & 63;
    g_h[i] += fmaxf(fmaf(u[i], scale[c], shift[c]), 0.f);
}

// ---------------- column sums of h (for graph mean) ----------------
__global__ void colsum_kernel(int N) {
    __shared__ double s[Dd];
    int tid = threadIdx.x;
    if (tid < Dd) s[tid] = 0.0;
    __syncthreads();
    int c = tid & 63;
    int rowsPerBlk = blockDim.x >> 6;
    float part = 0.f;
    for (int n = blockIdx.x * rowsPerBlk + (tid >> 6); n < N; n += gridDim.x * rowsPerBlk)
        part += g_h[(size_t)n * Dd + c];
    atomicAdd(&s[c], (double)part);
    __syncthreads();
    if (tid < Dd) atomicAdd(&g_sum[tid], s[tid]);
}

__global__ void graph_out_kernel(const float* __restrict__ gw, const float* __restrict__ gb,
                                 float* __restrict__ out, double invN) {
    __shared__ float partial[Dd];
    int c = threadIdx.x;
    if (c < Dd) {
        partial[c] = (float)(g_sum[c] * invN) * gw[c];
        g_sum[c] = 0.0;
    }
    __syncthreads();
    if (c == 0) {
        float s = 0.f;
        for (int i = 0; i < Dd; i++) s += partial[i];
        out[0] = s + gb[0];
    }
}

__global__ void node_out_kernel(const float* __restrict__ nw, const float* __restrict__ nb,
                                float* __restrict__ out, int N) {
    int idx = blockIdx.x * blockDim.x + threadIdx.x;
    if (idx >= N * 5) return;
    int n = idx / 5, o = idx - n * 5;
    float acc = nb[o];
    const float* hr = g_h + (size_t)n * Dd;
#pragma unroll 8
    for (int k = 0; k < Dd; k++) acc = fmaf(hr[k], nw[k * 5 + o], acc);
    out[idx] = acc;
}

__global__ void copy_h_kernel(float* __restrict__ out, int total) {
    int i = blockIdx.x * blockDim.x + threadIdx.x;
    if (i < total) out[i] = g_h[i];
}

// ---------------- host launcher ----------------
extern "C" void kernel_launch(void* const* d_in, const int* in_sizes, int n_in,
                              void* d_out, int out_size) {
    const float* x       = (const float*)d_in[0];
    const int*   ei      = (const int*)d_in[1];
    const float* eattr   = (const float*)d_in[2];
    const float* prev_h  = (const float*)d_in[3];
    const float* lin_in_w = (const float*)d_in[4];
    const float* lin_in_b = (const float*)d_in[5];
    const float* hist_w   = (const float*)d_in[6];
    const float* hist_b   = (const float*)d_in[7];
    const float* msg_w1 = (const float*)d_in[8];
    const float* msg_b1 = (const float*)d_in[9];
    const float* msg_g1 = (const float*)d_in[10];
    const float* msg_be1 = (const float*)d_in[11];
    const float* msg_w2 = (const float*)d_in[12];
    const float* msg_b2 = (const float*)d_in[13];
    const float* msg_g2 = (const float*)d_in[14];
    const float* msg_be2 = (const float*)d_in[15];
    const float* upd_w1 = (const float*)d_in[16];
    const float* upd_b1 = (const float*)d_in[17];
    const float* upd_g1 = (const float*)d_in[18];
    const float* upd_be1 = (const float*)d_in[19];
    const float* upd_w2 = (const float*)d_in[20];
    const float* upd_b2 = (const float*)d_in[21];
    const float* upd_g2 = (const float*)d_in[22];
    const float* upd_be2 = (const float*)d_in[23];
    const float* graph_w = (const float*)d_in[24];
    const float* graph_b = (const float*)d_in[25];
    const float* node_w  = (const float*)d_in[26];
    const float* node_b  = (const float*)d_in[27];

    const int N = in_sizes[0] / 11;
    const int E = in_sizes[1] / 2;
    const int* src = ei;       // edge_index[0]
    const int* dst = ei + E;   // edge_index[1]

    float* out = (float*)d_out;
    float* out_graph = out;
    float* out_node = out + 1;
    float* out_h = out + 1 + (size_t)N * 5;

    float *p_h, *p_aggr, *p_u, *p_m, *p_scale, *p_shift;
    cudaGetSymbolAddress((void**)&p_h, g_h);
    cudaGetSymbolAddress((void**)&p_aggr, g_aggr);
    cudaGetSymbolAddress((void**)&p_u, g_u);
    cudaGetSymbolAddress((void**)&p_m, g_m);
    cudaGetSymbolAddress((void**)&p_scale, g_scale);
    cudaGetSymbolAddress((void**)&p_shift, g_shift);

    // dynamic smem: TE*(K/4+1)*16 + K*64*4 + 2*64*8 + 2*128*4
    const int s132 = TE * 34 * 16 + 132 * 256 + 1024 + 1024;   // 105472
    const int s128 = TE * 33 * 16 + 128 * 256 + 1024 + 1024;   // 102400
    const int s64  = TE * 17 * 16 + 64 * 256 + 1024 + 1024;    //  53248
    cudaFuncSetAttribute(gemm_bn_kernel<132, 0>, cudaFuncAttributeMaxDynamicSharedMemorySize, s132);
    cudaFuncSetAttribute(gemm_bn_kernel<128, 2>, cudaFuncAttributeMaxDynamicSharedMemorySize, s128);
    cudaFuncSetAttribute(gemm_bn_kernel<64, 1>,  cudaFuncAttributeMaxDynamicSharedMemorySize, s64);

    const int tilesE = (E + TE - 1) / TE;
    const int tilesN = (N + TE - 1) / TE;
    const int gE132 = tilesE < 296 ? tilesE : 296;   // 2 blocks/SM (smem-limited)
    const int gE64  = tilesE < 592 ? tilesE : 592;   // 4 blocks/SM
    const int gN128 = tilesN < 296 ? tilesN : 296;
    const int gN64  = tilesN < 592 ? tilesN : 592;

    const double invE = 1.0 / (double)E;
    const double invN = 1.0 / (double)N;

    // h0
    init_h_kernel<<<(N * Dd + 255) / 256, 256>>>(x, prev_h, lin_in_w, lin_in_b, hist_w, hist_b, N);

    for (int l = 0; l < 4; l++) {
        // ---- message MLP stage 1 ----
        gemm_bn_kernel<132, 0><<<gE132, 128, s132>>>(
            msg_w1 + (size_t)l * 132 * Dd, msg_b1 + l * Dd,
            p_h, eattr, dst, src, nullptr, nullptr, p_m, E);
        finalize_bn_kernel<<<1, 64>>>(msg_g1 + l * Dd, msg_be1 + l * Dd, invE);

        // ---- message MLP stage 2 (in-place over g_m) ----
        gemm_bn_kernel<64, 1><<<gE64, 128, s64>>>(
            msg_w2 + (size_t)l * 64 * Dd, msg_b2 + l * Dd,
            p_m, nullptr, nullptr, nullptr, p_scale, p_shift, p_m, E);
        finalize_bn_kernel<<<1, 64>>>(msg_g2 + l * Dd, msg_be2 + l * Dd, invE);

        // ---- aggr = segment_sum(bn_relu(m2), dst) ----
        zero_aggr_kernel<<<(N * Dd + 255) / 256, 256>>>(N * Dd);
        scatter_kernel<<<(E * 16 + 255) / 256, 256>>>(p_m, dst, p_scale, p_shift, E);

        // ---- update MLP stage 1 ----
        gemm_bn_kernel<128, 2><<<gN128, 128, s128>>>(
            upd_w1 + (size_t)l * 128 * Dd, upd_b1 + l * Dd,
            p_h, p_aggr, nullptr, nullptr, nullptr, nullptr, p_u, N);
        finalize_bn_kernel<<<1, 64>>>(upd_g1 + l * Dd, upd_be1 + l * Dd, invN);

        // ---- update MLP stage 2 (in-place over g_u) ----
        gemm_bn_kernel<64, 1><<<gN64, 128, s64>>>(
            upd_w2 + (size_t)l * 64 * Dd, upd_b2 + l * Dd,
            p_u, nullptr, nullptr, nullptr, p_scale, p_shift, p_u, N);
        finalize_bn_kernel<<<1, 64>>>(upd_g2 + l * Dd, upd_be2 + l * Dd, invN);

        // ---- h += relu(affine(u2)) ----
        h_update_kernel<<<(N * Dd + 255) / 256, 256>>>(p_u, p_scale, p_shift, N * Dd);
    }

    // ---- outputs ----
    colsum_kernel<<<444, 256>>>(N);
    graph_out_kernel<<<1, 64>>>(graph_w, graph_b, out_graph, invN);
    node_out_kernel<<<(N * 5 + 255) / 256, 256>>>(node_w, node_b, out_node, N);
    copy_h_kernel<<<(N * Dd + 255) / 256, 256>>>(out_h, N * Dd);
}